// round 2
// baseline (speedup 1.0000x reference)
#include <cuda_runtime.h>
#include <math.h>

// ---------------- static scratch (no allocations allowed) ----------------
#define NSP 524288            // 32*32*32*16 points per (b,c)
#define NCH 20
#define NB  2
#define NMODE 24576           // 16*16*16*6 kept modes

__device__ float  g_hA[NB*NCH*NSP];          // 84 MB
__device__ float  g_hB[NB*NCH*NSP];          // 84 MB
__device__ float2 g_fa[10485760];            // 84 MB  (stage A / fwdZ out / invZ out / invX out)
__device__ float2 g_fb[5242880];             // 42 MB  (fwdY out / invY out)
__device__ float2 g_fd[NB*NCH*NMODE];        // 7.9 MB (x_ft at kept modes)
__device__ float2 g_fe[NB*NCH*NMODE];        // 7.9 MB (out_ft at kept modes)

// twiddle tables
__device__ float2 d_fwdX[512];   // [m(16)][x(32)]  e^{-2pi i k_m x/32},  k_m = m + (m>=8)*16
__device__ float2 d_fwdT[96];    // [k(6)][t(16)]   e^{-2pi i k t/16}
__device__ float2 d_invX[512];   // [x(32)][m(16)]  (1/32) e^{+2pi i k_m x/32}
__device__ float2 d_invT[96];    // [t(16)][k(6)]   ((k==0?1:2)/16) * (cos, sin)(+2pi k t/16)

__device__ __forceinline__ float gelu_exact(float v) {
    return 0.5f * v * (1.0f + erff(v * 0.70710678118654752f));
}

// ---------------- init twiddles (runs every launch, deterministic) -------
__global__ void k_init() {
    int tid = threadIdx.x;
    if (tid < 512) {
        int m = tid >> 5, x = tid & 31;
        int k = m + (m >= 8 ? 16 : 0);
        int ph = (k * x) & 31;
        float s, c; sincospif(-(float)ph / 16.0f, &s, &c);
        d_fwdX[tid] = make_float2(c, s);

        int z = tid >> 4, mm = tid & 15;
        int k2 = mm + (mm >= 8 ? 16 : 0);
        int ph2 = (k2 * z) & 31;
        float s2, c2; sincospif((float)ph2 / 16.0f, &s2, &c2);
        d_invX[tid] = make_float2(c2 * (1.0f/32.0f), s2 * (1.0f/32.0f));
    }
    if (tid < 96) {
        int k = tid / 16, t = tid & 15;
        int ph = (k * t) & 15;
        float s, c; sincospif(-(float)ph / 8.0f, &s, &c);
        d_fwdT[tid] = make_float2(c, s);

        int t2 = tid / 6, k2 = tid % 6;
        int ph2 = (k2 * t2) & 15;
        float wk = (k2 == 0 ? 1.0f : 2.0f) * (1.0f/16.0f);
        float s2, c2; sincospif((float)ph2 / 8.0f, &s2, &c2);
        d_invT[tid] = make_float2(wk * c2, wk * s2);
    }
}

// ---------------- lift: [B,X,Y,Z,T,5] -> h[b,c,p] --------------------------
__global__ void __launch_bounds__(256) k_lift(const float* __restrict__ x,
                                              const float* __restrict__ w,
                                              const float* __restrict__ bias) {
    int tid = blockIdx.x * blockDim.x + threadIdx.x;      // 0 .. 2*524288
    if (tid >= NB * NSP) return;
    int b = tid / NSP, p = tid % NSP;
    float xi[5];
#pragma unroll
    for (int i = 0; i < 5; i++) xi[i] = x[(size_t)tid * 5 + i];
#pragma unroll
    for (int c = 0; c < NCH; c++) {
        float a = __ldg(&bias[c]);
#pragma unroll
        for (int i = 0; i < 5; i++) a += xi[i] * __ldg(&w[i * NCH + c]);
        g_hA[(size_t)(b * NCH + c) * NSP + p] = a;
    }
}

// ---------------- forward DFT X (real -> 16 modes) -------------------------
__global__ void __launch_bounds__(256) k_fwdX(int src) {
    int tid = blockIdx.x * blockDim.x + threadIdx.x;      // 40*32*512 = 655360
    if (tid >= NB*NCH*32*512) return;
    int zt = tid & 511, y = (tid >> 9) & 31, bc = tid >> 14;
    const float* h = src ? g_hB : g_hA;
    const float* s = h + (size_t)bc * NSP + y * 512 + zt;
    float2 acc[16];
#pragma unroll
    for (int m = 0; m < 16; m++) acc[m] = make_float2(0.f, 0.f);
    for (int xx = 0; xx < 32; xx++) {
        float v = s[xx * 16384];
#pragma unroll
        for (int m = 0; m < 16; m++) {
            float2 w = d_fwdX[m * 32 + xx];
            acc[m].x += v * w.x; acc[m].y += v * w.y;
        }
    }
#pragma unroll
    for (int m = 0; m < 16; m++)
        g_fa[((size_t)(bc * 16 + m)) * 16384 + y * 512 + zt] = acc[m];
}

// ---------------- forward DFT Y -------------------------------------------
__global__ void __launch_bounds__(256) k_fwdY() {
    int tid = blockIdx.x * blockDim.x + threadIdx.x;      // 40*16*512 = 327680
    if (tid >= NB*NCH*16*512) return;
    int zt = tid & 511, kx = (tid >> 9) & 15, bc = tid >> 13;
    const float2* s = g_fa + ((size_t)(bc * 16 + kx)) * 16384 + zt;
    float2 acc[16];
#pragma unroll
    for (int m = 0; m < 16; m++) acc[m] = make_float2(0.f, 0.f);
    for (int y = 0; y < 32; y++) {
        float2 v = s[y * 512];
#pragma unroll
        for (int m = 0; m < 16; m++) {
            float2 w = d_fwdX[m * 32 + y];
            acc[m].x += v.x * w.x - v.y * w.y;
            acc[m].y += v.x * w.y + v.y * w.x;
        }
    }
#pragma unroll
    for (int m = 0; m < 16; m++)
        g_fb[(((size_t)(bc * 16 + kx)) * 16 + m) * 512 + zt] = acc[m];
}

// ---------------- forward DFT Z -------------------------------------------
__global__ void __launch_bounds__(256) k_fwdZ() {
    int tid = blockIdx.x * blockDim.x + threadIdx.x;      // 40*16*16*16 = 163840
    if (tid >= NB*NCH*16*16*16) return;
    int t = tid & 15, ky = (tid >> 4) & 15, kx = (tid >> 8) & 15, bc = tid >> 12;
    const float2* s = g_fb + ((((size_t)bc * 16 + kx)) * 16 + ky) * 512 + t;
    float2 acc[16];
#pragma unroll
    for (int m = 0; m < 16; m++) acc[m] = make_float2(0.f, 0.f);
    for (int z = 0; z < 32; z++) {
        float2 v = s[z * 16];
#pragma unroll
        for (int m = 0; m < 16; m++) {
            float2 w = d_fwdX[m * 32 + z];
            acc[m].x += v.x * w.x - v.y * w.y;
            acc[m].y += v.x * w.y + v.y * w.x;
        }
    }
#pragma unroll
    for (int m = 0; m < 16; m++)
        g_fa[(((((size_t)bc * 16 + kx) * 16 + ky) * 16 + m)) * 16 + t] = acc[m];
}

// ---------------- forward DFT T (16 -> 6 modes) -----------------------------
__global__ void __launch_bounds__(256) k_fwdT() {
    int tid = blockIdx.x * blockDim.x + threadIdx.x;      // 40*4096 = 163840
    if (tid >= NB*NCH*4096) return;
    const float2* s = g_fa + (size_t)tid * 16;
    float2 v[16];
#pragma unroll
    for (int t = 0; t < 16; t++) v[t] = s[t];
#pragma unroll
    for (int k = 0; k < 6; k++) {
        float2 acc = make_float2(0.f, 0.f);
#pragma unroll
        for (int t = 0; t < 16; t++) {
            float2 w = d_fwdT[k * 16 + t];
            acc.x += v[t].x * w.x - v[t].y * w.y;
            acc.y += v[t].x * w.y + v[t].y * w.x;
        }
        g_fd[(size_t)tid * 6 + k] = acc;
    }
}

// ---------------- spectral channel mix (per octant weights) ----------------
__global__ void __launch_bounds__(256) k_mult(const float2* __restrict__ swl) {
    int m = blockIdx.x * blockDim.x + threadIdx.x;        // 24576 modes
    if (m >= NMODE) return;
    int kt = m % 6; int r = m / 6;
    int kz = r & 15, ky = (r >> 4) & 15, kx = (r >> 8) & 15;
    int oct = ((kx >> 3) << 2) | ((ky >> 3) << 1) | (kz >> 3);
    int lm = (((kx & 7) * 8 + (ky & 7)) * 8 + (kz & 7)) * 6 + kt;
    const float2* wbase = swl + (size_t)oct * 1228800 + lm;   // float2 units

    float a0x[NCH], a0y[NCH], a1x[NCH], a1y[NCH];
#pragma unroll
    for (int o = 0; o < NCH; o++) { a0x[o]=a0y[o]=a1x[o]=a1y[o]=0.f; }

    for (int i = 0; i < NCH; i++) {
        float2 x0 = g_fd[(size_t)i * NMODE + m];
        float2 x1 = g_fd[(size_t)(NCH + i) * NMODE + m];
        const float2* wp = wbase + (size_t)i * 61440;
#pragma unroll
        for (int o = 0; o < NCH; o++) {
            float2 w = wp[o * 3072];
            a0x[o] += w.x * x0.x - w.y * x0.y;
            a0y[o] += w.x * x0.y + w.y * x0.x;
            a1x[o] += w.x * x1.x - w.y * x1.y;
            a1y[o] += w.x * x1.y + w.y * x1.x;
        }
    }
#pragma unroll
    for (int o = 0; o < NCH; o++) {
        g_fe[(size_t)o * NMODE + m]          = make_float2(a0x[o], a0y[o]);
        g_fe[(size_t)(NCH + o) * NMODE + m]  = make_float2(a1x[o], a1y[o]);
    }
}

// ---------------- inverse Z (16 modes -> 32) --------------------------------
__global__ void __launch_bounds__(256) k_invZ() {
    int tid = blockIdx.x * blockDim.x + threadIdx.x;      // 40*16*16*32*6 = 1966080
    if (tid >= NB*NCH*16*16*32*6) return;
    int kt = tid % 6; int r = tid / 6;
    int z = r & 31, ky = (r >> 5) & 15, kx = (r >> 9) & 15, bo = r >> 13;
    float2 acc = make_float2(0.f, 0.f);
    const float2* s = g_fe + (size_t)bo * NMODE + ((kx * 16 + ky) * 16) * 6 + kt;
#pragma unroll
    for (int kz = 0; kz < 16; kz++) {
        float2 v = s[kz * 6];
        float2 w = d_invX[z * 16 + kz];
        acc.x += v.x * w.x - v.y * w.y;
        acc.y += v.x * w.y + v.y * w.x;
    }
    g_fa[tid] = acc;   // layout (((bo*16+kx)*16+ky)*32+z)*6+kt
}

// ---------------- inverse Y -------------------------------------------------
__global__ void __launch_bounds__(256) k_invY() {
    int tid = blockIdx.x * blockDim.x + threadIdx.x;      // 40*16*32*32*6 = 3932160
    if (tid >= NB*NCH*16*32*32*6) return;
    int kt = tid % 6; int r = tid / 6;
    int z = r & 31, y = (r >> 5) & 31, kx = (r >> 10) & 15, bo = r >> 14;
    float2 acc = make_float2(0.f, 0.f);
    const float2* s = g_fa + ((((size_t)bo * 16 + kx) * 16) * 32 + z) * 6 + kt;
#pragma unroll
    for (int ky = 0; ky < 16; ky++) {
        float2 v = s[(size_t)ky * 192];
        float2 w = d_invX[y * 16 + ky];
        acc.x += v.x * w.x - v.y * w.y;
        acc.y += v.x * w.y + v.y * w.x;
    }
    g_fb[tid] = acc;   // layout (((bo*16+kx)*32+y)*32+z)*6+kt
}

// ---------------- inverse X -------------------------------------------------
__global__ void __launch_bounds__(256) k_invX() {
    int tid = blockIdx.x * blockDim.x + threadIdx.x;      // 40*32*32*32*6 = 7864320
    if (tid >= NB*NCH*32*32*32*6) return;
    int kt = tid % 6; int r = tid / 6;
    int z = r & 31, y = (r >> 5) & 31, xx = (r >> 10) & 31, bo = r >> 15;
    float2 acc = make_float2(0.f, 0.f);
    const float2* s = g_fb + ((((size_t)bo * 16) * 32 + y) * 32 + z) * 6 + kt;
#pragma unroll
    for (int kx = 0; kx < 16; kx++) {
        float2 v = s[(size_t)kx * 6144];
        float2 w = d_invX[xx * 16 + kx];
        acc.x += v.x * w.x - v.y * w.y;
        acc.y += v.x * w.y + v.y * w.x;
    }
    g_fa[tid] = acc;   // layout (((bo*32+x)*32+y)*32+z)*6+kt
}

// ---------------- fused inverse-T + pointwise (W h + b) + GELU -------------
__global__ void __launch_bounds__(256) k_fused(const float* __restrict__ ww,
                                               const float* __restrict__ wb,
                                               int src, int do_gelu) {
    __shared__ float  hs[NCH][256];
    __shared__ float2 gcs[NCH * 96];   // [o][sl*6+k]
    __shared__ float  sww[400];
    __shared__ float  swb[NCH];
    __shared__ float2 itw[96];

    const float* hin  = src ? g_hB : g_hA;
    float*       hout = src ? g_hA : g_hB;

    int b = blockIdx.x >> 11;                   // 2 batches
    int sbase = (blockIdx.x & 2047) * 16;       // 16 spatial positions / block
    int tid = threadIdx.x;

#pragma unroll
    for (int i = 0; i < NCH; i++)
        hs[i][tid] = hin[(size_t)(b * NCH + i) * NSP + sbase * 16 + tid];
    for (int q = tid; q < NCH * 96; q += 256) {
        int o = q / 96, r = q % 96; int sl = r / 6, k = r % 6;
        gcs[q] = g_fa[((size_t)(b * NCH + o) * 32768 + sbase + sl) * 6 + k];
    }
    for (int q = tid; q < 400; q += 256) sww[q] = ww[q];   // FIXED: was if(tid<400)
    if (tid < NCH) swb[tid] = wb[tid];
    if (tid < 96)  itw[tid] = d_invT[tid];
    __syncthreads();

    int sl = tid >> 4, t = tid & 15;
    float hv[NCH];
#pragma unroll
    for (int i = 0; i < NCH; i++) hv[i] = hs[i][tid];

#pragma unroll 4
    for (int o = 0; o < NCH; o++) {
        float acc = swb[o];
#pragma unroll
        for (int i = 0; i < NCH; i++) acc += sww[o * NCH + i] * hv[i];
        float h1 = 0.f;
#pragma unroll
        for (int k = 0; k < 6; k++) {
            float2 w = itw[t * 6 + k];
            float2 g = gcs[o * 96 + sl * 6 + k];
            h1 += g.x * w.x - g.y * w.y;
        }
        float v = acc + h1;
        if (do_gelu) v = gelu_exact(v);
        hout[(size_t)(b * NCH + o) * NSP + (sbase + sl) * 16 + t] = v;
    }
}

// ---------------- head: fc1(20->128) + GELU + fc2(128->1) ------------------
__global__ void __launch_bounds__(256) k_head(const float* __restrict__ fc1w,
                                              const float* __restrict__ fc1b,
                                              const float* __restrict__ fc2w,
                                              const float* __restrict__ fc2b,
                                              float* __restrict__ out) {
    __shared__ float hs[NCH][256];
    __shared__ float w1[NCH * 128];
    __shared__ float b1[128], w2[128];

    int b = blockIdx.x >> 11;
    int pbase = (blockIdx.x & 2047) * 256;
    int tid = threadIdx.x;

#pragma unroll
    for (int i = 0; i < NCH; i++)
        hs[i][tid] = g_hA[(size_t)(b * NCH + i) * NSP + pbase + tid];
    for (int q = tid; q < NCH * 128; q += 256) w1[q] = fc1w[q];
    if (tid < 128) { b1[tid] = fc1b[tid]; w2[tid] = fc2w[tid]; }
    __syncthreads();

    float hv[NCH];
#pragma unroll
    for (int i = 0; i < NCH; i++) hv[i] = hs[i][tid];

    float acc = __ldg(&fc2b[0]);
#pragma unroll 4
    for (int j = 0; j < 128; j++) {
        float a = b1[j];
#pragma unroll
        for (int i = 0; i < NCH; i++) a += hv[i] * w1[i * 128 + j];
        a = gelu_exact(a);
        acc += a * w2[j];
    }
    out[(size_t)b * NSP + pbase + tid] = acc;
}

// ---------------- launch ----------------------------------------------------
extern "C" void kernel_launch(void* const* d_in, const int* in_sizes, int n_in,
                              void* d_out, int out_size) {
    const float* x     = (const float*)d_in[0];
    const float* fc0_w = (const float*)d_in[1];
    const float* fc0_b = (const float*)d_in[2];
    const float* sw    = (const float*)d_in[3];
    const float* ww    = (const float*)d_in[4];
    const float* wb    = (const float*)d_in[5];
    const float* fc1_w = (const float*)d_in[6];
    const float* fc1_b = (const float*)d_in[7];
    const float* fc2_w = (const float*)d_in[8];
    const float* fc2_b = (const float*)d_in[9];
    float* out = (float*)d_out;

    k_init<<<1, 512>>>();
    k_lift<<<4096, 256>>>(x, fc0_w, fc0_b);

    int src = 0;
    for (int l = 0; l < 4; l++) {
        k_fwdX<<<2560, 256>>>(src);
        k_fwdY<<<1280, 256>>>();
        k_fwdZ<<<640, 256>>>();
        k_fwdT<<<640, 256>>>();
        const float2* swl = (const float2*)sw + (size_t)l * 9830400;
        k_mult<<<96, 256>>>(swl);
        k_invZ<<<7680, 256>>>();
        k_invY<<<15360, 256>>>();
        k_invX<<<30720, 256>>>();
        k_fused<<<4096, 256>>>(ww + l * 400, wb + l * NCH, src, (l < 3) ? 1 : 0);
        src ^= 1;
    }
    // after 4 layers src == 0 -> result in g_hA
    k_head<<<4096, 256>>>(fc1_w, fc1_b, fc2_w, fc2_b, out);
}